// round 10
// baseline (speedup 1.0000x reference)
#include <cuda_runtime.h>

// grid [2,160,160,160,3] float32
#define BB 2
#define NX 160
#define NY 160
#define NZ 160

#define TY 12
#define NCHUNK 6                  // z chunks, 28 outputs each (168 >= 156)
#define XSPLIT 6
#define XSTEPS 26                 // 156 / XSPLIT
#define NTHREADS (TY*32)          // 384
#define NBLOCKS (NCHUNK*13*BB*XSPLIT) // 936

#define RY (TY + 4)               // 16
#define RZ_ST 32                  // staged z per slice
#define SLICE (RY * RZ_ST * 3)    // 1536 floats
#define ROWW (NZ * 3)             // 480 floats per (b,x,y) row
#define CPR (RZ_ST * 3 / 4)       // 24 16B chunks per staged row

__device__ double g_be_sum;
__device__ unsigned int g_be_cnt;

__device__ __forceinline__ void cp16(unsigned int dst_smem, const float* src) {
    asm volatile("cp.async.cg.shared.global [%0], [%1], 16;" :: "r"(dst_smem), "l"(src));
}
__device__ __forceinline__ void cp_commit() {
    asm volatile("cp.async.commit_group;" ::: "memory");
}
__device__ __forceinline__ void cp_wait0() {
    asm volatile("cp.async.wait_group 0;" ::: "memory");
}
__device__ __forceinline__ void cp_wait1() {
    asm volatile("cp.async.wait_group 1;" ::: "memory");
}

#define SHUP(v)  __shfl_up_sync(0xffffffffu, (v), 1)
#define SHDN(v)  __shfl_down_sync(0xffffffffu, (v), 1)
#define SHUP2(v) __shfl_up_sync(0xffffffffu, (v), 2)
#define SHDN2(v) __shfl_down_sync(0xffffffffu, (v), 2)

__global__ __launch_bounds__(NTHREADS, 4)
void be_main_kernel(const float* __restrict__ g, float* __restrict__ out) {
    __shared__ float ring[4 * SLICE];       // read set {x+2} only -> 4 slots
    __shared__ float warp_part[NTHREADS / 32];

    const int tz  = threadIdx.x;            // 0..31 (lane)
    const int ty  = threadIdx.y;            // 0..11
    const int tid = ty * 32 + tz;

    const int cz  = blockIdx.x;             // 0..5   z chunk (28 outputs each)
    const int cy  = blockIdx.y;             // 0..12
    const int b   = blockIdx.z / XSPLIT;
    const int seg = blockIdx.z % XSPLIT;

    const int z0 = 2 + cz * 28;
    const int y0 = 2 + cy * TY;
    const int xs = 2 + seg * XSTEPS;

    const int zc = z0 - 2 + tz;
    const bool active = (tz >= 2) && (tz <= 29) && (zc <= NZ - 3);

    // ---- staging map: exactly one 16B chunk per thread ----
    const int zbase3 = (z0 - 2) * 3;
    int goff;
    {
        int row = tid / CPR, col = tid - row * CPR;
        int o = zbase3 + col * 4;
        if (o > ROWW - 4) o = ROWW - 4;     // clamp: lands in unread lane-halo slack
        goff = row * ROWW + o;
    }

    const long long bbase = (long long)b * NX * NY * ROWW + (long long)(y0 - 2) * ROWW;
    const unsigned int ring_s = (unsigned int)__cvta_generic_to_shared(ring);

    auto issue_slice = [&](int gx, int slot) {
        const float* src = g + bbase + (long long)gx * (NY * ROWW);
        cp16(ring_s + (unsigned int)(slot * SLICE) * 4u + (unsigned int)tid * 16u,
             src + goff);
    };

    // ---- slot(gx) = (gx - xs + 2) mod 4; prologue: xs-2..xs+1 -> slots 0..3 ----
    issue_slice(xs - 2, 0);
    issue_slice(xs - 1, 1);
    issue_slice(xs,     2);
    issue_slice(xs + 1, 3);
    cp_commit();
    cp_wait0();
    __syncthreads();

    const int off0 = ((ty + 2) * RZ_ST + tz) * 3;
    #define Y (RZ_ST * 3)

    // delay lines
    float c0a, c0b, c0c, c0d, c0e;          // comp0 centers x+1..x-2 (+junk)
    float c1p2, c1p1, c1z;                  // comp1 centers x+1, x, x-1
    float c2p2, c2p1, c2z;                  // comp2
    float qa0, qa1, qa2, qb0, qb1, qb2, qc0, qc1, qc2;  // q_xy at x+1, x, x-1
    float syA0, syA1, syB0, syB1;           // y-sums (c0,c1) for slices x, x+1
    {
        const float* s;
        s = ring + 3 * SLICE;               // xs+1
        c0a = s[off0]; c1p2 = s[off0 + 1]; c2p2 = s[off0 + 2];
        qa0 = s[off0 + Y]     - s[off0 - Y];
        qa1 = s[off0 + Y + 1] - s[off0 - Y + 1];
        qa2 = s[off0 + Y + 2] - s[off0 - Y + 2];
        syB0 = s[off0 + 2*Y]     + s[off0 - 2*Y];
        syB1 = s[off0 + 2*Y + 1] + s[off0 - 2*Y + 1];
        s = ring + 2 * SLICE;               // xs
        c0b = s[off0]; c1p1 = s[off0 + 1]; c2p1 = s[off0 + 2];
        qb0 = s[off0 + Y]     - s[off0 - Y];
        qb1 = s[off0 + Y + 1] - s[off0 - Y + 1];
        qb2 = s[off0 + Y + 2] - s[off0 - Y + 2];
        syA0 = s[off0 + 2*Y]     + s[off0 - 2*Y];
        syA1 = s[off0 + 2*Y + 1] + s[off0 - 2*Y + 1];
        s = ring + 1 * SLICE;               // xs-1
        c0c = s[off0]; c1z = s[off0 + 1]; c2z = s[off0 + 2];
        qc0 = s[off0 + Y]     - s[off0 - Y];
        qc1 = s[off0 + Y + 1] - s[off0 - Y + 1];
        qc2 = s[off0 + Y + 2] - s[off0 - Y + 2];
        s = ring;                           // xs-2
        c0d = s[off0];
        c0e = 0.f;
    }
    __syncthreads();            // init reads done before slot reuse

    // pipeline: xs+2 -> slot 0, xs+3 -> slot 1 (two groups in flight)
    issue_slice(xs + 2, 0); cp_commit();
    issue_slice(xs + 3, 1); cp_commit();

    float acc = 0.0f;
    int gx4 = xs + 4;

    // step i: SP2 slot = i%4 (slice x+2), STG slot = (i+2)%4 (held x, dead)
    #define DO_STEP(STGi, SP2i)                                                   \
    {                                                                             \
        cp_wait1();                                                               \
        __syncthreads();                                                          \
        {                                                                         \
            int gxs = gx4 > (NX - 1) ? (NX - 1) : gx4;                            \
            issue_slice(gxs, (STGi)); cp_commit(); ++gx4;                         \
        }                                                                         \
        const float* Sp = ring + (SP2i) * SLICE;  /* slice x+2 (fresh) */         \
        const float n0 = Sp[off0], n1 = Sp[off0 + 1], n2 = Sp[off0 + 2];          \
        const float qf0 = Sp[off0 + Y]     - Sp[off0 - Y];                        \
        const float qf1 = Sp[off0 + Y + 1] - Sp[off0 - Y + 1];                    \
        const float qf2 = Sp[off0 + Y + 2] - Sp[off0 - Y + 2];                    \
        const float g0  = Sp[off0 + 2*Y]     + Sp[off0 - 2*Y];                    \
        const float g1  = Sp[off0 + 2*Y + 1] + Sp[off0 - 2*Y + 1];                \
        const float c1m = c1z, c2m = c2z;         /* x-1 comps 1,2 */             \
        c0e = c0d; c0d = c0c; c0c = c0b; c0b = c0a; c0a = n0;                     \
        c1z = c1p1; c1p1 = c1p2; c1p2 = n1;       /* c1z -> x */                  \
        c2z = c2p1; c2p1 = c2p2; c2p2 = n2;                                       \
        const float d0 = c0b - c0d, d1 = c1p1 - c1m, d2 = c2p1 - c2m;             \
        const float dxz0 = SHDN(d0) - SHUP(d0);                                   \
        const float dxz1 = SHDN(d1) - SHUP(d1);                                   \
        const float dxz2 = SHDN(d2) - SHUP(d2);                                   \
        const float dyz0 = SHDN(qb0) - SHUP(qb0);                                 \
        const float dyz1 = SHDN(qb1) - SHUP(qb1);                                 \
        const float dyz2 = SHDN(qb2) - SHUP(qb2);                                 \
        const float dzz0 = SHUP2(c0c) + SHDN2(c0c) - 2.0f * c0c;                  \
        const float dzz1 = SHUP2(c1z) + SHDN2(c1z) - 2.0f * c1z;                  \
        const float dzz2 = SHUP2(c2z) + SHDN2(c2z) - 2.0f * c2z;                  \
        if (active) {                                                             \
            const float dxx0 = c0e + c0a - 2.0f * c0c;                            \
            const float dyy0 = syA0 - 2.0f * c0c;                                 \
            const float dyy1 = syA1 - 2.0f * c1z;                                 \
            const float dxy0 = qa0 - qc0;                                         \
            const float dxy1 = qa1 - qc1;                                         \
            float v = dxx0 * dxx0;                                                \
            v = fmaf(2.0f * dyy0, dyy0, v);                                       \
            v = fmaf(2.0f * dzz0, dzz0, v);                                       \
            v = fmaf(3.0f * dxy0, dxy0, v);                                       \
            v = fmaf(3.0f * dxz0, dxz0, v);                                       \
            v = fmaf(4.0f * dyz0, dyz0, v);                                       \
            v = fmaf(dyy1, dyy1, v);                                              \
            v = fmaf(2.0f * dzz1, dzz1, v);                                       \
            v = fmaf(dxy1, dxy1, v);                                              \
            v = fmaf(2.0f * dxz1, dxz1, v);                                       \
            v = fmaf(3.0f * dyz1, dyz1, v);                                       \
            v = fmaf(dzz2, dzz2, v);                                              \
            v = fmaf(dxz2, dxz2, v);                                              \
            v = fmaf(dyz2, dyz2, v);                                              \
            acc += v;                                                             \
        }                                                                         \
        qc0 = qb0; qc1 = qb1; qc2 = qb2;                                          \
        qb0 = qa0; qb1 = qa1; qb2 = qa2;                                          \
        qa0 = qf0; qa1 = qf1; qa2 = qf2;                                          \
        syA0 = syB0; syA1 = syB1; syB0 = g0; syB1 = g1;                           \
    }

    // 26 steps = 6 x 4 + 2; slot pattern period 4 (all literals)
    #pragma unroll 1
    for (int it = 0; it < 6; ++it) {
        DO_STEP(2, 0);
        DO_STEP(3, 1);
        DO_STEP(0, 2);
        DO_STEP(1, 3);
    }
    DO_STEP(2, 0);              // step 24
    DO_STEP(3, 1);              // step 25

    #undef DO_STEP
    #undef Y

    // block reduction
    float v = acc;
    #pragma unroll
    for (int o = 16; o > 0; o >>= 1) v += __shfl_down_sync(0xffffffffu, v, o);
    if ((tid & 31) == 0) warp_part[tid >> 5] = v;
    __syncthreads();
    if (tid == 0) {
        float s = 0.0f;
        #pragma unroll
        for (int w = 0; w < NTHREADS / 32; ++w) s += warp_part[w];
        atomicAdd(&g_be_sum, (double)s);
        __threadfence();
        unsigned int t = atomicAdd(&g_be_cnt, 1u);
        if (t == NBLOCKS - 1) {
            double total = atomicAdd(&g_be_sum, 0.0);   // ordered read of final sum
            const double n = (double)BB * 156.0 * 156.0 * 156.0 * 3.0;
            out[0] = (float)(total / (16.0 * n));
            g_be_cnt = 0;        // reset for next (graph-replayed) launch
            g_be_sum = 0.0;
        }
    }
}

extern "C" void kernel_launch(void* const* d_in, const int* in_sizes, int n_in,
                              void* d_out, int out_size) {
    const float* grid = (const float*)d_in[0];
    float* out = (float*)d_out;

    dim3 blk(32, TY, 1);
    dim3 grd(NCHUNK, 13, BB * XSPLIT);
    be_main_kernel<<<grd, blk>>>(grid, out);
}

// round 11
// speedup vs baseline: 1.0005x; 1.0005x over previous
#include <cuda_runtime.h>

// grid [2,160,160,160,3] float32
#define BB 2
#define NX 160
#define NY 160
#define NZ 160

#define TY 12
#define NCHUNK 3                  // z chunks of 60 outputs (lanes hold 2 z each)
#define XSPLIT 13
#define XSTEPS 12                 // 156 / 13
#define NTHREADS (TY*32)          // 384
#define NBLOCKS (NCHUNK*13*BB*XSPLIT) // 1014

#define RY (TY + 4)               // 16
#define ZW 64                     // staged z per slice (2 per lane)
#define SLICE (RY * ZW * 3)       // 3072 floats = 12KB
#define ROWW (NZ * 3)             // 480
#define CPR (ZW * 3 / 4)          // 48 16B chunks per staged row
#define Y (ZW * 3)                // 192: +1 y row in floats

__device__ double g_be_sum;
__device__ unsigned int g_be_cnt;

__device__ __forceinline__ void cp16(unsigned int dst_smem, const float* src) {
    asm volatile("cp.async.cg.shared.global [%0], [%1], 16;" :: "r"(dst_smem), "l"(src));
}
__device__ __forceinline__ void cp_commit() {
    asm volatile("cp.async.commit_group;" ::: "memory");
}
__device__ __forceinline__ void cp_wait0() {
    asm volatile("cp.async.wait_group 0;" ::: "memory");
}
__device__ __forceinline__ void cp_wait1() {
    asm volatile("cp.async.wait_group 1;" ::: "memory");
}

#define SHUP(v)  __shfl_up_sync(0xffffffffu, (v), 1)
#define SHDN(v)  __shfl_down_sync(0xffffffffu, (v), 1)

__device__ __forceinline__ float2 lds2(const float* p) {
    return *(const float2*)p;
}

__global__ __launch_bounds__(NTHREADS, 2)
void be_main_kernel(const float* __restrict__ g, float* __restrict__ out) {
    __shared__ float ring[4 * SLICE];       // 48KB exactly; reused for reduction
    float* warp_part = ring;                // aliased (after mainloop + barrier)

    const int tz  = threadIdx.x;            // lane
    const int ty  = threadIdx.y;
    const int tid = ty * 32 + tz;

    const int cz  = blockIdx.x;             // 0..2
    const int cy  = blockIdx.y;             // 0..12
    const int b   = blockIdx.z / XSPLIT;
    const int seg = blockIdx.z % XSPLIT;

    const int zb  = cz * 60;                // staged window [zb, zb+63]
    const int y0  = 2 + cy * TY;
    const int xs  = 2 + seg * XSTEPS;

    // lane holds cells zA = zb+2*tz, zB = zA+1; taps need lanes tz±1
    const int zA = zb + 2 * tz;
    const bool lane_ok = (tz >= 1) && (tz <= 30);
    const bool activeA = lane_ok && (zA     <= NZ - 3);
    const bool activeB = lane_ok && (zA + 1 <= NZ - 3);

    // ---- staging map: 2 x 16B chunks per thread per slice ----
    int goffA, goffB;
    {
        int j = tid;
        int row = j / CPR, col = j - row * CPR;
        int o = zb * 3 + col * 4;
        if (o > ROWW - 4) o = ROWW - 4;     // clamp: dup data lands in unread z>=160 cells
        goffA = row * ROWW + o;
        j = tid + NTHREADS;
        row = j / CPR; col = j - row * CPR;
        o = zb * 3 + col * 4;
        if (o > ROWW - 4) o = ROWW - 4;
        goffB = row * ROWW + o;
    }

    const long long bbase = (long long)b * NX * NY * ROWW + (long long)(y0 - 2) * ROWW;
    const unsigned int ring_s = (unsigned int)__cvta_generic_to_shared(ring);

    auto issue_slice = [&](int gx, int slot) {
        const float* src = g + bbase + (long long)gx * (NY * ROWW);
        unsigned int sb = ring_s + (unsigned int)(slot * SLICE) * 4u;
        cp16(sb + (unsigned int)tid * 16u, src + goffA);
        cp16(sb + (unsigned int)(tid + NTHREADS) * 16u, src + goffB);
    };

    // ---- slot(gx) = (gx - xs + 2) mod 4; prologue xs-2..xs+1 -> 0..3 ----
    issue_slice(xs - 2, 0);
    issue_slice(xs - 1, 1);
    issue_slice(xs,     2);
    issue_slice(xs + 1, 3);
    cp_commit();
    cp_wait0();
    __syncthreads();

    const int off0 = (ty + 2) * Y + 6 * tz;

    // ---- delay lines, per cell (A = zA, B = zA+1) ----
    float c0aA,c0bA,c0cA,c0dA,c0eA, c0aB,c0bB,c0cB,c0dB,c0eB;
    float c1p2A,c1p1A,c1zA, c1p2B,c1p1B,c1zB;
    float c2p2A,c2p1A,c2zA, c2p2B,c2p1B,c2zB;
    float qa0A,qa1A,qa2A, qa0B,qa1B,qa2B;
    float qb0A,qb1A,qb2A, qb0B,qb1B,qb2B;
    float qc0A,qc1A,qc2A, qc0B,qc1B,qc2B;
    float syA0A,syA1A, syA0B,syA1B, syB0A,syB1A, syB0B,syB1B;
    {
        const float* s;
        float2 a,bb,c, u0,u1,u2, l0,l1,l2;
        // slot 3 = xs+1
        s = ring + 3 * SLICE;
        a = lds2(s+off0); bb = lds2(s+off0+2); c = lds2(s+off0+4);
        c0aA=a.x; c1p2A=a.y; c2p2A=bb.x; c0aB=bb.y; c1p2B=c.x; c2p2B=c.y;
        u0=lds2(s+off0+Y); u1=lds2(s+off0+Y+2); u2=lds2(s+off0+Y+4);
        l0=lds2(s+off0-Y); l1=lds2(s+off0-Y+2); l2=lds2(s+off0-Y+4);
        qa0A=u0.x-l0.x; qa1A=u0.y-l0.y; qa2A=u1.x-l1.x;
        qa0B=u1.y-l1.y; qa1B=u2.x-l2.x; qa2B=u2.y-l2.y;
        u0=lds2(s+off0+2*Y); u1=lds2(s+off0+2*Y+2); u2=lds2(s+off0+2*Y+4);
        l0=lds2(s+off0-2*Y); l1=lds2(s+off0-2*Y+2); l2=lds2(s+off0-2*Y+4);
        syB0A=u0.x+l0.x; syB1A=u0.y+l0.y; syB0B=u1.y+l1.y; syB1B=u2.x+l2.x;
        // slot 2 = xs
        s = ring + 2 * SLICE;
        a = lds2(s+off0); bb = lds2(s+off0+2); c = lds2(s+off0+4);
        c0bA=a.x; c1p1A=a.y; c2p1A=bb.x; c0bB=bb.y; c1p1B=c.x; c2p1B=c.y;
        u0=lds2(s+off0+Y); u1=lds2(s+off0+Y+2); u2=lds2(s+off0+Y+4);
        l0=lds2(s+off0-Y); l1=lds2(s+off0-Y+2); l2=lds2(s+off0-Y+4);
        qb0A=u0.x-l0.x; qb1A=u0.y-l0.y; qb2A=u1.x-l1.x;
        qb0B=u1.y-l1.y; qb1B=u2.x-l2.x; qb2B=u2.y-l2.y;
        u0=lds2(s+off0+2*Y); u1=lds2(s+off0+2*Y+2); u2=lds2(s+off0+2*Y+4);
        l0=lds2(s+off0-2*Y); l1=lds2(s+off0-2*Y+2); l2=lds2(s+off0-2*Y+4);
        syA0A=u0.x+l0.x; syA1A=u0.y+l0.y; syA0B=u1.y+l1.y; syA1B=u2.x+l2.x;
        // slot 1 = xs-1
        s = ring + 1 * SLICE;
        a = lds2(s+off0); bb = lds2(s+off0+2); c = lds2(s+off0+4);
        c0cA=a.x; c1zA=a.y; c2zA=bb.x; c0cB=bb.y; c1zB=c.x; c2zB=c.y;
        u0=lds2(s+off0+Y); u1=lds2(s+off0+Y+2); u2=lds2(s+off0+Y+4);
        l0=lds2(s+off0-Y); l1=lds2(s+off0-Y+2); l2=lds2(s+off0-Y+4);
        qc0A=u0.x-l0.x; qc1A=u0.y-l0.y; qc2A=u1.x-l1.x;
        qc0B=u1.y-l1.y; qc1B=u2.x-l2.x; qc2B=u2.y-l2.y;
        // slot 0 = xs-2: comp0 centers only
        s = ring;
        a = lds2(s+off0); bb = lds2(s+off0+2);
        c0dA=a.x; c0dB=bb.y;
        c0eA=0.f; c0eB=0.f;
    }
    __syncthreads();            // init reads done before slot 0/1 reuse

    issue_slice(xs + 2, 0); cp_commit();
    issue_slice(xs + 3, 1); cp_commit();

    float acc = 0.0f;
    int gx4 = xs + 4;

    // step i: fresh slice x+2 in slot SP2i=i%4; stage x+4 into STGi=(i+2)%4 (held x, dead)
    #define DO_STEP(STGi, SP2i)                                                   \
    {                                                                             \
        cp_wait1();                                                               \
        __syncthreads();                                                          \
        {                                                                         \
            int gxs = gx4 > (NX - 1) ? (NX - 1) : gx4;                            \
            issue_slice(gxs, (STGi)); cp_commit(); ++gx4;                         \
        }                                                                         \
        const float* Sp = ring + (SP2i) * SLICE;                                  \
        float2 n01 = lds2(Sp+off0), n23 = lds2(Sp+off0+2), n45 = lds2(Sp+off0+4); \
        float2 u0 = lds2(Sp+off0+Y),   u1 = lds2(Sp+off0+Y+2),   u2 = lds2(Sp+off0+Y+4); \
        float2 l0 = lds2(Sp+off0-Y),   l1 = lds2(Sp+off0-Y+2),   l2 = lds2(Sp+off0-Y+4); \
        const float qf0A=u0.x-l0.x, qf1A=u0.y-l0.y, qf2A=u1.x-l1.x;               \
        const float qf0B=u1.y-l1.y, qf1B=u2.x-l2.x, qf2B=u2.y-l2.y;               \
        float2 U0 = lds2(Sp+off0+2*Y), U1 = lds2(Sp+off0+2*Y+2), U2 = lds2(Sp+off0+2*Y+4); \
        float2 L0 = lds2(Sp+off0-2*Y), L1 = lds2(Sp+off0-2*Y+2), L2 = lds2(Sp+off0-2*Y+4); \
        const float g0A=U0.x+L0.x, g1A=U0.y+L0.y, g0B=U1.y+L1.y, g1B=U2.x+L2.x;   \
        const float c1mA=c1zA, c2mA=c2zA, c1mB=c1zB, c2mB=c2zB;  /* x-1 */        \
        c0eA=c0dA; c0dA=c0cA; c0cA=c0bA; c0bA=c0aA; c0aA=n01.x;                   \
        c0eB=c0dB; c0dB=c0cB; c0cB=c0bB; c0bB=c0aB; c0aB=n23.y;                   \
        c1zA=c1p1A; c1p1A=c1p2A; c1p2A=n01.y;                                     \
        c1zB=c1p1B; c1p1B=c1p2B; c1p2B=n45.x;                                     \
        c2zA=c2p1A; c2p1A=c2p2A; c2p2A=n23.x;                                     \
        c2zB=c2p1B; c2p1B=c2p2B; c2p2B=n45.y;                                     \
        /* d = c(x+1)-c(x-1) per comp per cell */                                 \
        const float d0A=c0bA-c0dA, d1A=c1p1A-c1mA, d2A=c2p1A-c2mA;                \
        const float d0B=c0bB-c0dB, d1B=c1p1B-c1mB, d2B=c2p1B-c2mB;                \
        /* dxz: zA taps d at z+1 (=dB same lane), z-1 (=dB lane-1) */             \
        const float dxz0A = d0B - SHUP(d0B), dxz0B = SHDN(d0A) - d0A;             \
        const float dxz1A = d1B - SHUP(d1B), dxz1B = SHDN(d1A) - d1A;             \
        const float dxz2A = d2B - SHUP(d2B), dxz2B = SHDN(d2A) - d2A;             \
        /* dyz from q at slice x (qb) */                                          \
        const float dyz0A = qb0B - SHUP(qb0B), dyz0B = SHDN(qb0A) - qb0A;         \
        const float dyz1A = qb1B - SHUP(qb1B), dyz1B = SHDN(qb1A) - qb1A;         \
        const float dyz2A = qb2B - SHUP(qb2B), dyz2B = SHDN(qb2A) - qb2A;         \
        /* dzz: z+/-2 = same cell, lanes +/-1 */                                  \
        const float dzz0A = SHUP(c0cA)+SHDN(c0cA)-2.0f*c0cA;                      \
        const float dzz0B = SHUP(c0cB)+SHDN(c0cB)-2.0f*c0cB;                      \
        const float dzz1A = SHUP(c1zA)+SHDN(c1zA)-2.0f*c1zA;                      \
        const float dzz1B = SHUP(c1zB)+SHDN(c1zB)-2.0f*c1zB;                      \
        const float dzz2A = SHUP(c2zA)+SHDN(c2zA)-2.0f*c2zA;                      \
        const float dzz2B = SHUP(c2zB)+SHDN(c2zB)-2.0f*c2zB;                      \
        if (activeA) {                                                            \
            const float dxx0 = c0eA + c0aA - 2.0f*c0cA;                           \
            const float dyy0 = syA0A - 2.0f*c0cA;                                 \
            const float dyy1 = syA1A - 2.0f*c1zA;                                 \
            const float dxy0 = qa0A - qc0A;                                       \
            const float dxy1 = qa1A - qc1A;                                       \
            float v = dxx0*dxx0;                                                  \
            v = fmaf(2.0f*dyy0, dyy0, v);                                         \
            v = fmaf(2.0f*dzz0A, dzz0A, v);                                       \
            v = fmaf(3.0f*dxy0, dxy0, v);                                         \
            v = fmaf(3.0f*dxz0A, dxz0A, v);                                       \
            v = fmaf(4.0f*dyz0A, dyz0A, v);                                       \
            v = fmaf(dyy1, dyy1, v);                                              \
            v = fmaf(2.0f*dzz1A, dzz1A, v);                                       \
            v = fmaf(dxy1, dxy1, v);                                              \
            v = fmaf(2.0f*dxz1A, dxz1A, v);                                       \
            v = fmaf(3.0f*dyz1A, dyz1A, v);                                       \
            v = fmaf(dzz2A, dzz2A, v);                                            \
            v = fmaf(dxz2A, dxz2A, v);                                            \
            v = fmaf(dyz2A, dyz2A, v);                                            \
            acc += v;                                                             \
        }                                                                         \
        if (activeB) {                                                            \
            const float dxx0 = c0eB + c0aB - 2.0f*c0cB;                           \
            const float dyy0 = syA0B - 2.0f*c0cB;                                 \
            const float dyy1 = syA1B - 2.0f*c1zB;                                 \
            const float dxy0 = qa0B - qc0B;                                       \
            const float dxy1 = qa1B - qc1B;                                       \
            float v = dxx0*dxx0;                                                  \
            v = fmaf(2.0f*dyy0, dyy0, v);                                         \
            v = fmaf(2.0f*dzz0B, dzz0B, v);                                       \
            v = fmaf(3.0f*dxy0, dxy0, v);                                         \
            v = fmaf(3.0f*dxz0B, dxz0B, v);                                       \
            v = fmaf(4.0f*dyz0B, dyz0B, v);                                       \
            v = fmaf(dyy1, dyy1, v);                                              \
            v = fmaf(2.0f*dzz1B, dzz1B, v);                                       \
            v = fmaf(dxy1, dxy1, v);                                              \
            v = fmaf(2.0f*dxz1B, dxz1B, v);                                       \
            v = fmaf(3.0f*dyz1B, dyz1B, v);                                       \
            v = fmaf(dzz2B, dzz2B, v);                                            \
            v = fmaf(dxz2B, dxz2B, v);                                            \
            v = fmaf(dyz2B, dyz2B, v);                                            \
            acc += v;                                                             \
        }                                                                         \
        qc0A=qb0A; qc1A=qb1A; qc2A=qb2A; qc0B=qb0B; qc1B=qb1B; qc2B=qb2B;         \
        qb0A=qa0A; qb1A=qa1A; qb2A=qa2A; qb0B=qa0B; qb1B=qa1B; qb2B=qa2B;         \
        qa0A=qf0A; qa1A=qf1A; qa2A=qf2A; qa0B=qf0B; qa1B=qf1B; qa2B=qf2B;         \
        syA0A=syB0A; syA1A=syB1A; syA0B=syB0B; syA1B=syB1B;                       \
        syB0A=g0A;  syB1A=g1A;  syB0B=g0B;  syB1B=g1B;                            \
    }

    // 12 steps = 3 x 4; slot pattern period 4 (all literals)
    #pragma unroll 1
    for (int it = 0; it < 3; ++it) {
        DO_STEP(2, 0);
        DO_STEP(3, 1);
        DO_STEP(0, 2);
        DO_STEP(1, 3);
    }

    #undef DO_STEP

    // block reduction (ring reused as scratch after barrier)
    __syncthreads();
    float v = acc;
    #pragma unroll
    for (int o = 16; o > 0; o >>= 1) v += __shfl_down_sync(0xffffffffu, v, o);
    if (tz == 0) warp_part[ty] = v;
    __syncthreads();
    if (tid == 0) {
        float s = 0.0f;
        #pragma unroll
        for (int w = 0; w < TY; ++w) s += warp_part[w];
        atomicAdd(&g_be_sum, (double)s);
        __threadfence();
        unsigned int t = atomicAdd(&g_be_cnt, 1u);
        if (t == NBLOCKS - 1) {
            double total = atomicAdd(&g_be_sum, 0.0);
            const double n = (double)BB * 156.0 * 156.0 * 156.0 * 3.0;
            out[0] = (float)(total / (16.0 * n));
            g_be_cnt = 0;
            g_be_sum = 0.0;
        }
    }
}

extern "C" void kernel_launch(void* const* d_in, const int* in_sizes, int n_in,
                              void* d_out, int out_size) {
    const float* grid = (const float*)d_in[0];
    float* out = (float*)d_out;

    dim3 blk(32, TY, 1);
    dim3 grd(NCHUNK, 13, BB * XSPLIT);
    be_main_kernel<<<grd, blk>>>(grid, out);
}

// round 12
// speedup vs baseline: 1.1136x; 1.1130x over previous
#include <cuda_runtime.h>

// grid [2,160,160,160,3] float32
#define BB 2
#define NX 160
#define NY 160
#define NZ 160

#define TY 12
#define NCHUNK 6                  // z chunks, 28 outputs each (168 >= 156)
#define XSPLIT 6
#define XSTEPS 26                 // 156 / XSPLIT
#define NTHREADS (TY*32)          // 384
#define NBLOCKS (NCHUNK*13*BB*XSPLIT) // 936

#define RY (TY + 4)               // 16
#define RZ_ST 32                  // staged z per slice (z0-2 .. z0+29)
#define SLICE (RY * RZ_ST * 3)    // 1536 floats
#define ROWW (NZ * 3)             // 480 floats per (b,x,y) row
#define CPR (RZ_ST * 3 / 4)       // 24 16B chunks per staged row

__device__ double g_be_sum;
__device__ unsigned int g_be_cnt;

__device__ __forceinline__ void cp16(unsigned int dst_smem, const float* src) {
    asm volatile("cp.async.cg.shared.global [%0], [%1], 16;" :: "r"(dst_smem), "l"(src));
}
__device__ __forceinline__ void cp_commit() {
    asm volatile("cp.async.commit_group;" ::: "memory");
}
__device__ __forceinline__ void cp_wait0() {
    asm volatile("cp.async.wait_group 0;" ::: "memory");
}
__device__ __forceinline__ void cp_wait1() {
    asm volatile("cp.async.wait_group 1;" ::: "memory");
}

#define SHUP(v)  __shfl_up_sync(0xffffffffu, (v), 1)
#define SHDN(v)  __shfl_down_sync(0xffffffffu, (v), 1)
#define SHUP2(v) __shfl_up_sync(0xffffffffu, (v), 2)
#define SHDN2(v) __shfl_down_sync(0xffffffffu, (v), 2)

__global__ __launch_bounds__(NTHREADS, 3)
void be_main_kernel(const float* __restrict__ g, float* __restrict__ out) {
    __shared__ float ring[5 * SLICE];
    __shared__ float warp_part[NTHREADS / 32];

    const int tz  = threadIdx.x;            // 0..31 (lane)
    const int ty  = threadIdx.y;            // 0..11
    const int tid = ty * 32 + tz;

    const int cz  = blockIdx.x;             // 0..5   z chunk (28 outputs each)
    const int cy  = blockIdx.y;             // 0..12
    const int b   = blockIdx.z / XSPLIT;
    const int seg = blockIdx.z % XSPLIT;

    const int z0 = 2 + cz * 28;             // first output z of this chunk
    const int y0 = 2 + cy * TY;
    const int xs = 2 + seg * XSTEPS;

    // lane l holds center z = z0 - 2 + l; outputs come from lanes 2..29
    const int zc = z0 - 2 + tz;
    const bool active = (tz >= 2) && (tz <= 29) && (zc <= NZ - 3);

    // ---- staging map: exactly one 16B chunk per thread ----
    const int zbase3 = (z0 - 2) * 3;        // = 84*cz, 16B-aligned
    int goff;
    {
        int row = tid / CPR, col = tid - row * CPR;
        int o = zbase3 + col * 4;
        if (o > ROWW - 4) o = ROWW - 4;     // clamp: lands in unread lane-halo slack
        goff = row * ROWW + o;
    }

    const long long bbase = (long long)b * NX * NY * ROWW + (long long)(y0 - 2) * ROWW;
    const unsigned int ring_s = (unsigned int)__cvta_generic_to_shared(ring);

    auto issue_slice = [&](int gx, int slot) {
        const float* src = g + bbase + (long long)gx * (NY * ROWW);
        cp16(ring_s + (unsigned int)(slot * SLICE) * 4u + (unsigned int)tid * 16u,
             src + goff);
    };

    // ---- slot(x) = (x - xs + 2) mod 5; prologue: xs-2..xs+1 -> slots 0..3 ----
    issue_slice(xs - 2, 0);
    issue_slice(xs - 1, 1);
    issue_slice(xs,     2);
    issue_slice(xs + 1, 3);
    cp_commit();
    cp_wait0();
    __syncthreads();

    const int off0 = ((ty + 2) * RZ_ST + tz) * 3;
    #define Y (RZ_ST * 3)
    #define Zw 3

    // center delay lines: c0 x+2..x-2; c1,c2 x+2..x
    float c0a, c0b, c0c, c0d, c0e;
    float c1p2, c1p1, c1z, c2p2, c2p1, c2z;
    // q delay lines: q(s) = S_s[+off] - S_s[-off]
    float q2_xy0, q2_xy1, q2_xz0, q2_xz1, q2_xz2;
    float q1_xy0, q1_xy1, q1_xy2, q1_xz0, q1_xz1, q1_xz2;
    {
        const float* s;
        s = ring + 3 * SLICE; c0a = s[off0]; c1p2 = s[off0 + 1]; c2p2 = s[off0 + 2]; // xs+1
        s = ring + 2 * SLICE; c0b = s[off0]; c1p1 = s[off0 + 1]; c2p1 = s[off0 + 2]; // xs
        q1_xy0 = s[off0 + Y]      - s[off0 - Y];
        q1_xy1 = s[off0 + Y + 1]  - s[off0 - Y + 1];
        q1_xy2 = s[off0 + Y + 2]  - s[off0 - Y + 2];
        q1_xz0 = s[off0 + Zw]     - s[off0 - Zw];
        q1_xz1 = s[off0 + Zw + 1] - s[off0 - Zw + 1];
        q1_xz2 = s[off0 + Zw + 2] - s[off0 - Zw + 2];
        s = ring + 1 * SLICE; c0c = s[off0];                                          // xs-1
        q2_xy0 = s[off0 + Y]      - s[off0 - Y];
        q2_xy1 = s[off0 + Y + 1]  - s[off0 - Y + 1];
        q2_xz0 = s[off0 + Zw]     - s[off0 - Zw];
        q2_xz1 = s[off0 + Zw + 1] - s[off0 - Zw + 1];
        q2_xz2 = s[off0 + Zw + 2] - s[off0 - Zw + 2];
        s = ring;             c0d = s[off0];                                          // xs-2
        c0e = 0.f; c1z = 0.f; c2z = 0.f;
    }
    __syncthreads();            // init reads done before slot 0/4 reuse

    // pipeline: xs+2 -> slot 4, xs+3 -> slot 0 (two groups in flight)
    issue_slice(xs + 2, 4); cp_commit();
    issue_slice(xs + 3, 0); cp_commit();

    float acc = 0.0f;
    int gx4 = xs + 4;

    #define DO_STEP(SM1i, S0i, SP1i, SP2i)                                        \
    {                                                                             \
        cp_wait1();                                                               \
        __syncthreads();                                                          \
        {                                                                         \
            int gxs = gx4 > (NX - 1) ? (NX - 1) : gx4;                            \
            issue_slice(gxs, (SM1i)); cp_commit(); ++gx4;                         \
        }                                                                         \
        {                                                                         \
            const float* sp = ring + (SP2i) * SLICE;                              \
            float n0 = sp[off0], n1 = sp[off0 + 1], n2 = sp[off0 + 2];            \
            c0e = c0d; c0d = c0c; c0c = c0b; c0b = c0a; c0a = n0;                 \
            c1z = c1p1; c1p1 = c1p2; c1p2 = n1;                                   \
            c2z = c2p1; c2p1 = c2p2; c2p2 = n2;                                   \
        }                                                                         \
        const float* Sp1 = ring + (SP1i) * SLICE;                                 \
        const float qn_xy0 = Sp1[off0 + Y]     - Sp1[off0 - Y];                   \
        const float qn_xy1 = Sp1[off0 + Y + 1] - Sp1[off0 - Y + 1];               \
        const float qn_xy2 = Sp1[off0 + Y + 2] - Sp1[off0 - Y + 2];               \
        const float qn_xz0 = SHDN(c0b)  - SHUP(c0b);                              \
        const float qn_xz1 = SHDN(c1p1) - SHUP(c1p1);                             \
        const float qn_xz2 = SHDN(c2p1) - SHUP(c2p1);                             \
        const float dyz0 = SHDN(q1_xy0) - SHUP(q1_xy0);                           \
        const float dyz1 = SHDN(q1_xy1) - SHUP(q1_xy1);                           \
        const float dyz2 = SHDN(q1_xy2) - SHUP(q1_xy2);                           \
        const float dzz0 = SHUP2(c0c) + SHDN2(c0c) - 2.0f * c0c;                  \
        const float dzz1 = SHUP2(c1z) + SHDN2(c1z) - 2.0f * c1z;                  \
        const float dzz2 = SHUP2(c2z) + SHDN2(c2z) - 2.0f * c2z;                  \
        if (active) {                                                             \
            const float* S0 = ring + (S0i) * SLICE;                               \
            const float dxx0 = c0e + c0a - 2.0f * c0c;                            \
            const float dyy0 = S0[off0 - 2*Y]     + S0[off0 + 2*Y]     - 2.0f * c0c; \
            const float dyy1 = S0[off0 - 2*Y + 1] + S0[off0 + 2*Y + 1] - 2.0f * c1z; \
            const float dxy0 = qn_xy0 - q2_xy0;                                   \
            const float dxy1 = qn_xy1 - q2_xy1;                                   \
            const float dxz0 = qn_xz0 - q2_xz0;                                   \
            const float dxz1 = qn_xz1 - q2_xz1;                                   \
            const float dxz2 = qn_xz2 - q2_xz2;                                   \
            /* weight-grouped sums: 4 independent chains, 3 combine FMAs */       \
            float s1 = dxx0 * dxx0;                                               \
            s1 = fmaf(dyy1, dyy1, s1);                                            \
            s1 = fmaf(dxy1, dxy1, s1);                                            \
            s1 = fmaf(dzz2, dzz2, s1);                                            \
            s1 = fmaf(dxz2, dxz2, s1);                                            \
            s1 = fmaf(dyz2, dyz2, s1);                                            \
            float s2 = dyy0 * dyy0;                                               \
            s2 = fmaf(dzz0, dzz0, s2);                                            \
            s2 = fmaf(dzz1, dzz1, s2);                                            \
            s2 = fmaf(dxz1, dxz1, s2);                                            \
            float s3 = dxy0 * dxy0;                                               \
            s3 = fmaf(dxz0, dxz0, s3);                                            \
            s3 = fmaf(dyz1, dyz1, s3);                                            \
            float t = fmaf(2.0f, s2, s1);                                         \
            t = fmaf(3.0f, s3, t);                                                \
            t = fmaf(4.0f * dyz0, dyz0, t);                                       \
            acc += t;                                                             \
        }                                                                         \
        q2_xy0 = q1_xy0; q2_xy1 = q1_xy1;                                         \
        q2_xz0 = q1_xz0; q2_xz1 = q1_xz1; q2_xz2 = q1_xz2;                        \
        q1_xy0 = qn_xy0; q1_xy1 = qn_xy1; q1_xy2 = qn_xy2;                        \
        q1_xz0 = qn_xz0; q1_xz1 = qn_xz1; q1_xz2 = qn_xz2;                        \
    }

    // 26 steps = 5 x 5 + 1 tail; slot pattern period 5 (all literals)
    #pragma unroll 1
    for (int it = 0; it < 5; ++it) {
        DO_STEP(1, 2, 3, 4);
        DO_STEP(2, 3, 4, 0);
        DO_STEP(3, 4, 0, 1);
        DO_STEP(4, 0, 1, 2);
        DO_STEP(0, 1, 2, 3);
    }
    DO_STEP(1, 2, 3, 4);        // step 25

    #undef DO_STEP
    #undef Y
    #undef Zw

    // block reduction
    float v = acc;
    #pragma unroll
    for (int o = 16; o > 0; o >>= 1) v += __shfl_down_sync(0xffffffffu, v, o);
    if ((tid & 31) == 0) warp_part[tid >> 5] = v;
    __syncthreads();
    if (tid == 0) {
        float s = 0.0f;
        #pragma unroll
        for (int w = 0; w < NTHREADS / 32; ++w) s += warp_part[w];
        atomicAdd(&g_be_sum, (double)s);
        __threadfence();
        unsigned int t = atomicAdd(&g_be_cnt, 1u);
        if (t == NBLOCKS - 1) {
            double total = atomicAdd(&g_be_sum, 0.0);   // ordered read of final sum
            const double n = (double)BB * 156.0 * 156.0 * 156.0 * 3.0;
            out[0] = (float)(total / (16.0 * n));
            g_be_cnt = 0;        // reset for next (graph-replayed) launch
            g_be_sum = 0.0;
        }
    }
}

extern "C" void kernel_launch(void* const* d_in, const int* in_sizes, int n_in,
                              void* d_out, int out_size) {
    const float* grid = (const float*)d_in[0];
    float* out = (float*)d_out;

    dim3 blk(32, TY, 1);
    dim3 grd(NCHUNK, 13, BB * XSPLIT);
    be_main_kernel<<<grd, blk>>>(grid, out);
}